// round 1
// baseline (speedup 1.0000x reference)
#include <cuda_runtime.h>
#include <cuda_bf16.h>
#include <mma.h>

using namespace nvcuda;

#define NTILES 128
#define C_DIM  256
#define I_DIM  128
#define HW_DIM 1024
#define KP_DIM 256

// Scratch (static device globals -- allowed; no runtime allocation)
__device__ __nv_bfloat16 g_theta[(size_t)NTILES * I_DIM * HW_DIM];  // [tile][i][hw]  32MB
__device__ __nv_bfloat16 g_phi  [(size_t)NTILES * I_DIM * KP_DIM];  // [tile][i][k]    8MB
__device__ __nv_bfloat16 g_gg   [(size_t)NTILES * I_DIM * KP_DIM];  // [tile][i][k]    8MB
__device__ __nv_bfloat16 g_y    [(size_t)NTILES * HW_DIM * I_DIM];  // [tile][hw][i]  32MB

// ---------------------------------------------------------------------------
// Kernel 1: theta/phi/g 1x1 convs (GEMM) + fused 2x2 maxpool for phi/g.
// grid = (nb:4 hw-blocks of 256, mb:3 {theta,phi,g}, tile:128), 256 threads.
// CTA GEMM: M=128 (out ch), N=256 (hw), K=256 (in ch), bf16 wmma, fp32 accum.
// ---------------------------------------------------------------------------
__global__ __launch_bounds__(256) void conv3_kernel(
    const float* __restrict__ x,
    const float* __restrict__ tw, const float* __restrict__ tb,
    const float* __restrict__ pw, const float* __restrict__ pb,
    const float* __restrict__ gw, const float* __restrict__ gb)
{
    extern __shared__ char smem[];
    float*         sO = reinterpret_cast<float*>(smem);                           // [128][256] f32 (128KB)
    __nv_bfloat16* sA = reinterpret_cast<__nv_bfloat16*>(smem + 131072);          // [128][64]  (16KB)
    __nv_bfloat16* sB = reinterpret_cast<__nv_bfloat16*>(smem + 131072 + 16384);  // [64][256]  (32KB)

    const int nb   = blockIdx.x;
    const int mb   = blockIdx.y;
    const int tile = blockIdx.z;
    const int b = tile >> 4, t = tile & 15;
    const int bs1 = t >> 2, bs2 = t & 3;
    const int tid = threadIdx.x;
    const int warp = tid >> 5;
    const int wr = warp >> 2, wc = warp & 3;

    const float* W  = (mb == 0) ? tw : ((mb == 1) ? pw : gw);
    const float* BV = (mb == 0) ? tb : ((mb == 1) ? pb : gb);

    wmma::fragment<wmma::accumulator, 16, 16, 16, float> acc[4][4];
    #pragma unroll
    for (int i = 0; i < 4; i++)
        #pragma unroll
        for (int j = 0; j < 4; j++) wmma::fill_fragment(acc[i][j], 0.0f);

    // x tile element (c, p, q) lives at xbase + c*16384 + p*128 + q
    const float* xbase = x + (size_t)b * C_DIM * 16384 + bs1 * 32 * 128 + bs2 * 32;
    const int p0 = nb * 8;   // this CTA covers rows p0..p0+7 of the 32x32 tile

    for (int kc = 0; kc < 4; kc++) {           // K chunks of 64
        // stage A: W[0..127][kc*64 .. +64]
        #pragma unroll
        for (int it = 0; it < 32; it++) {
            int lin = it * 256 + tid;
            int r = lin >> 6, ci = lin & 63;
            sA[lin] = __float2bfloat16(W[r * C_DIM + kc * 64 + ci]);
        }
        // stage B: x[c=kc*64.. , hw block of 256] (float4 loads)
        #pragma unroll
        for (int it = 0; it < 16; it++) {
            int lin = it * 256 + tid;          // float4 index among 4096
            int r = lin >> 6;
            int j = (lin & 63) * 4;
            int pp = p0 + (j >> 5);
            int qq = j & 31;
            float4 v = *reinterpret_cast<const float4*>(
                xbase + (size_t)(kc * 64 + r) * 16384 + pp * 128 + qq);
            int o = r * 256 + j;
            sB[o + 0] = __float2bfloat16(v.x);
            sB[o + 1] = __float2bfloat16(v.y);
            sB[o + 2] = __float2bfloat16(v.z);
            sB[o + 3] = __float2bfloat16(v.w);
        }
        __syncthreads();
        #pragma unroll
        for (int kk = 0; kk < 4; kk++) {
            wmma::fragment<wmma::matrix_a, 16, 16, 16, __nv_bfloat16, wmma::row_major> fa[4];
            wmma::fragment<wmma::matrix_b, 16, 16, 16, __nv_bfloat16, wmma::row_major> fb[4];
            #pragma unroll
            for (int i = 0; i < 4; i++)
                wmma::load_matrix_sync(fa[i], sA + (wr * 64 + i * 16) * 64 + kk * 16, 64);
            #pragma unroll
            for (int j = 0; j < 4; j++)
                wmma::load_matrix_sync(fb[j], sB + (kk * 16) * 256 + wc * 64 + j * 16, 256);
            #pragma unroll
            for (int i = 0; i < 4; i++)
                #pragma unroll
                for (int j = 0; j < 4; j++)
                    wmma::mma_sync(acc[i][j], fa[i], fb[j], acc[i][j]);
        }
        __syncthreads();
    }

    #pragma unroll
    for (int i = 0; i < 4; i++)
        #pragma unroll
        for (int j = 0; j < 4; j++)
            wmma::store_matrix_sync(sO + (wr * 64 + i * 16) * 256 + wc * 64 + j * 16,
                                    acc[i][j], 256, wmma::mem_row_major);
    __syncthreads();

    if (mb == 0) {
        // theta: full-res, + bias, -> bf16 scratch [tile][o][hw]
        __nv_bfloat16* dst = g_theta + (size_t)tile * I_DIM * HW_DIM + nb * 256;
        for (int it = 0; it < 64; it++) {
            int lin = it * 256 + tid;          // bf16x2 index among 16384
            int o = lin >> 7;
            int j = (lin & 127) * 2;
            float bias = BV[o];
            float v0 = sO[o * 256 + j] + bias;
            float v1 = sO[o * 256 + j + 1] + bias;
            *reinterpret_cast<__nv_bfloat162*>(dst + (size_t)o * HW_DIM + j) =
                __floats2bfloat162_rn(v0, v1);
        }
    } else {
        // phi / g: 2x2 maxpool fused (pool(conv)+b == pool(conv+b))
        __nv_bfloat16* dst = ((mb == 1) ? g_phi : g_gg) + (size_t)tile * I_DIM * KP_DIM;
        for (int it = 0; it < 32; it++) {
            int lin = it * 256 + tid;          // 128 o * 4 rr * 16 s = 8192
            int o  = lin >> 6;
            int rr = (lin >> 4) & 3;
            int s  = lin & 15;
            const float* row = sO + o * 256 + rr * 64 + 2 * s;
            float m = fmaxf(fmaxf(row[0], row[1]), fmaxf(row[32], row[33]));
            dst[o * KP_DIM + (p0 / 2 + rr) * 16 + s] = __float2bfloat16(m + BV[o]);
        }
    }
}

// ---------------------------------------------------------------------------
// Kernel 2: per (tile, q-block of 128):
//   S[128,256] = theta_blk^T @ phi   (fp32 accum in smem)
//   softmax rows (fp32, warp shuffles)
//   y[128,128] = F @ g^T             -> g_y bf16
// smem: sS f32 128KB | sF(phi->F) bf16 64KB | sT bf16 32KB ; sG/sY alias sS.
// ---------------------------------------------------------------------------
__global__ __launch_bounds__(256) void attn_kernel()
{
    extern __shared__ char smem[];
    float*         sS = reinterpret_cast<float*>(smem);                            // [128][256] f32
    __nv_bfloat16* sF = reinterpret_cast<__nv_bfloat16*>(smem + 131072);           // [128][256] phi -> F
    __nv_bfloat16* sT = reinterpret_cast<__nv_bfloat16*>(smem + 131072 + 65536);   // [128 i][128 q]
    __nv_bfloat16* sG = reinterpret_cast<__nv_bfloat16*>(smem);                    // alias: [128 io][256 k]
    float*         sY = reinterpret_cast<float*>(smem + 65536);                    // alias: [128][128] f32

    const int qb   = blockIdx.x;
    const int tile = blockIdx.y;
    const int tid = threadIdx.x;
    const int warp = tid >> 5, lane = tid & 31;
    const int wr = warp >> 2, wc = warp & 3;

    // stage theta block as col-major A: sT[i*128 + q]
    {
        const __nv_bfloat16* thp = g_theta + (size_t)tile * I_DIM * HW_DIM + qb * 128;
        uint4* d = reinterpret_cast<uint4*>(sT);
        for (int it = 0; it < 8; it++) {
            int lin = it * 256 + tid;           // uint4 idx among 2048 (16 per row)
            int i = lin >> 4;
            int qv = lin & 15;
            d[lin] = *reinterpret_cast<const uint4*>(thp + (size_t)i * HW_DIM + qv * 8);
        }
    }
    // stage phi [128][256] bf16
    {
        const uint4* s = reinterpret_cast<const uint4*>(g_phi + (size_t)tile * I_DIM * KP_DIM);
        uint4* d = reinterpret_cast<uint4*>(sF);
        for (int it = 0; it < 16; it++) d[it * 256 + tid] = s[it * 256 + tid];
    }
    __syncthreads();

    // GEMM1: S = A(col_major, ld 128) x B(row_major, ld 256), K=128
    {
        wmma::fragment<wmma::accumulator, 16, 16, 16, float> acc[4][4];
        #pragma unroll
        for (int i = 0; i < 4; i++)
            #pragma unroll
            for (int j = 0; j < 4; j++) wmma::fill_fragment(acc[i][j], 0.0f);
        #pragma unroll
        for (int kk = 0; kk < 8; kk++) {
            wmma::fragment<wmma::matrix_a, 16, 16, 16, __nv_bfloat16, wmma::col_major> fa[4];
            wmma::fragment<wmma::matrix_b, 16, 16, 16, __nv_bfloat16, wmma::row_major> fb[4];
            #pragma unroll
            for (int i = 0; i < 4; i++)
                wmma::load_matrix_sync(fa[i], sT + (kk * 16) * 128 + wr * 64 + i * 16, 128);
            #pragma unroll
            for (int j = 0; j < 4; j++)
                wmma::load_matrix_sync(fb[j], sF + (kk * 16) * 256 + wc * 64 + j * 16, 256);
            #pragma unroll
            for (int i = 0; i < 4; i++)
                #pragma unroll
                for (int j = 0; j < 4; j++)
                    wmma::mma_sync(acc[i][j], fa[i], fb[j], acc[i][j]);
        }
        #pragma unroll
        for (int i = 0; i < 4; i++)
            #pragma unroll
            for (int j = 0; j < 4; j++)
                wmma::store_matrix_sync(sS + (wr * 64 + i * 16) * 256 + wc * 64 + j * 16,
                                        acc[i][j], 256, wmma::mem_row_major);
    }
    __syncthreads();

    // softmax over k=256 per row (fp32); write F bf16 into sF (phi dead)
    for (int rr = 0; rr < 16; rr++) {
        int row = warp * 16 + rr;
        float v[8];
        float m = -1e30f;
        #pragma unroll
        for (int u = 0; u < 8; u++) { v[u] = sS[row * 256 + u * 32 + lane]; m = fmaxf(m, v[u]); }
        #pragma unroll
        for (int off = 16; off > 0; off >>= 1) m = fmaxf(m, __shfl_xor_sync(0xffffffffu, m, off));
        float ssum = 0.f;
        #pragma unroll
        for (int u = 0; u < 8; u++) { v[u] = __expf(v[u] - m); ssum += v[u]; }
        #pragma unroll
        for (int off = 16; off > 0; off >>= 1) ssum += __shfl_xor_sync(0xffffffffu, ssum, off);
        float inv = 1.0f / ssum;
        #pragma unroll
        for (int u = 0; u < 8; u++)
            sF[row * 256 + u * 32 + lane] = __float2bfloat16(v[u] * inv);
    }
    __syncthreads();

    // stage g [128 io][256 k] into sG (aliases dead sS bytes 0..64K)
    {
        const uint4* s = reinterpret_cast<const uint4*>(g_gg + (size_t)tile * I_DIM * KP_DIM);
        uint4* d = reinterpret_cast<uint4*>(sG);
        for (int it = 0; it < 16; it++) d[it * 256 + tid] = s[it * 256 + tid];
    }
    __syncthreads();

    // GEMM2: y[q, io] = F[q,k] * g[io,k]  (B col_major over stored [io][k], ld 256)
    {
        wmma::fragment<wmma::accumulator, 16, 16, 16, float> ac2[4][2];
        #pragma unroll
        for (int i = 0; i < 4; i++)
            #pragma unroll
            for (int j = 0; j < 2; j++) wmma::fill_fragment(ac2[i][j], 0.0f);
        #pragma unroll
        for (int kk = 0; kk < 16; kk++) {
            wmma::fragment<wmma::matrix_a, 16, 16, 16, __nv_bfloat16, wmma::row_major> fa[4];
            wmma::fragment<wmma::matrix_b, 16, 16, 16, __nv_bfloat16, wmma::col_major> fb[2];
            #pragma unroll
            for (int i = 0; i < 4; i++)
                wmma::load_matrix_sync(fa[i], sF + (wr * 64 + i * 16) * 256 + kk * 16, 256);
            #pragma unroll
            for (int j = 0; j < 2; j++)
                wmma::load_matrix_sync(fb[j], sG + (wc * 32 + j * 16) * 256 + kk * 16, 256);
            #pragma unroll
            for (int i = 0; i < 4; i++)
                #pragma unroll
                for (int j = 0; j < 2; j++)
                    wmma::mma_sync(ac2[i][j], fa[i], fb[j], ac2[i][j]);
        }
        #pragma unroll
        for (int i = 0; i < 4; i++)
            #pragma unroll
            for (int j = 0; j < 2; j++)
                wmma::store_matrix_sync(sY + (wr * 64 + i * 16) * 128 + wc * 32 + j * 16,
                                        ac2[i][j], 128, wmma::mem_row_major);
    }
    __syncthreads();

    // write y bf16 [tile][qb*128 + q][io]
    {
        __nv_bfloat16* yp = g_y + (size_t)tile * HW_DIM * I_DIM + (size_t)qb * 128 * I_DIM;
        for (int it = 0; it < 32; it++) {
            int lin = it * 256 + tid;           // bf16x2 pair among 8192
            reinterpret_cast<__nv_bfloat162*>(yp)[lin] =
                __floats2bfloat162_rn(sY[lin * 2], sY[lin * 2 + 1]);
        }
    }
}

// ---------------------------------------------------------------------------
// Kernel 3: wy = w_w @ y^T, fused BN + residual + output permutation.
// grid = (nb:8 hw-blocks of 128, tile:128). CTA GEMM: M=256, N=128, K=128.
// ---------------------------------------------------------------------------
__global__ __launch_bounds__(256) void out_kernel(
    const float* __restrict__ x, const float* __restrict__ ww, const float* __restrict__ wb,
    const float* __restrict__ gam, const float* __restrict__ bet,
    const float* __restrict__ mean, const float* __restrict__ var,
    float* __restrict__ out)
{
    extern __shared__ char smem[];
    float*         sO  = reinterpret_cast<float*>(smem);                           // [256][128] f32
    __nv_bfloat16* sW  = reinterpret_cast<__nv_bfloat16*>(smem + 131072);          // [256][128] bf16
    __nv_bfloat16* sYv = reinterpret_cast<__nv_bfloat16*>(smem + 131072 + 65536);  // [128 hw][128 i]

    const int nb   = blockIdx.x;
    const int tile = blockIdx.y;
    const int b = tile >> 4, t = tile & 15;
    const int bs1 = t >> 2, bs2 = t & 3;
    const int tid = threadIdx.x, warp = tid >> 5;
    const int wr = warp >> 1, wc = warp & 1;

    // stage W [256][128] f32 -> bf16
    for (int it = 0; it < 32; it++) {
        int lin = it * 256 + tid;               // float4 idx among 8192
        float4 v = reinterpret_cast<const float4*>(ww)[lin];
        reinterpret_cast<__nv_bfloat162*>(sW)[lin * 2 + 0] = __floats2bfloat162_rn(v.x, v.y);
        reinterpret_cast<__nv_bfloat162*>(sW)[lin * 2 + 1] = __floats2bfloat162_rn(v.z, v.w);
    }
    // stage y block [128 hw][128 i]
    {
        const uint4* s = reinterpret_cast<const uint4*>(
            g_y + (size_t)tile * HW_DIM * I_DIM + (size_t)nb * 128 * I_DIM);
        uint4* d = reinterpret_cast<uint4*>(sYv);
        for (int it = 0; it < 8; it++) d[it * 256 + tid] = s[it * 256 + tid];
    }
    __syncthreads();

    // GEMM: wy[o, hw] = sum_i W[o,i] * y[hw,i]  (B col_major over [hw][i], ld 128)
    {
        wmma::fragment<wmma::accumulator, 16, 16, 16, float> acc[4][4];
        #pragma unroll
        for (int i = 0; i < 4; i++)
            #pragma unroll
            for (int j = 0; j < 4; j++) wmma::fill_fragment(acc[i][j], 0.0f);
        #pragma unroll
        for (int kk = 0; kk < 8; kk++) {
            wmma::fragment<wmma::matrix_a, 16, 16, 16, __nv_bfloat16, wmma::row_major> fa[4];
            wmma::fragment<wmma::matrix_b, 16, 16, 16, __nv_bfloat16, wmma::col_major> fb[4];
            #pragma unroll
            for (int i = 0; i < 4; i++)
                wmma::load_matrix_sync(fa[i], sW + (wr * 64 + i * 16) * 128 + kk * 16, 128);
            #pragma unroll
            for (int j = 0; j < 4; j++)
                wmma::load_matrix_sync(fb[j], sYv + (wc * 64 + j * 16) * 128 + kk * 16, 128);
            #pragma unroll
            for (int i = 0; i < 4; i++)
                #pragma unroll
                for (int j = 0; j < 4; j++)
                    wmma::mma_sync(acc[i][j], fa[i], fb[j], acc[i][j]);
        }
        #pragma unroll
        for (int i = 0; i < 4; i++)
            #pragma unroll
            for (int j = 0; j < 4; j++)
                wmma::store_matrix_sync(sO + (wr * 64 + i * 16) * 128 + wc * 64 + j * 16,
                                        acc[i][j], 128, wmma::mem_row_major);
    }
    __syncthreads();

    // epilogue: BN + residual + permuted scatter
    const float* xbase = x + (size_t)b * C_DIM * 16384 + bs1 * 32 * 128 + bs2 * 32;
    float* obase = out + (size_t)b * C_DIM * 16384;
    for (int it = 0; it < 128; it++) {
        int lin = it * 256 + tid;
        int o  = lin >> 7;                      // 0..255 out channel
        int jl = lin & 127;
        int hw = nb * 128 + jl;
        int p = hw >> 5, q = hw & 31;
        float sc = gam[o] * rsqrtf(var[o] + 1e-5f);
        float base = (wb[o] - mean[o]) * sc + bet[o];
        float v = sO[lin] * sc + base + xbase[(size_t)o * 16384 + p * 128 + q];
        int co = t * 16 + (o >> 4);
        int oh = (o & 15) * 8 + (p >> 2);
        int ow = (p & 3) * 32 + q;
        obase[(size_t)co * 16384 + (size_t)oh * 128 + ow] = v;
    }
}

// ---------------------------------------------------------------------------
extern "C" void kernel_launch(void* const* d_in, const int* in_sizes, int n_in,
                              void* d_out, int out_size)
{
    const float* x    = (const float*)d_in[0];
    const float* tw   = (const float*)d_in[1];
    const float* tb   = (const float*)d_in[2];
    const float* pw   = (const float*)d_in[3];
    const float* pb   = (const float*)d_in[4];
    const float* gw   = (const float*)d_in[5];
    const float* gb   = (const float*)d_in[6];
    const float* ww   = (const float*)d_in[7];
    const float* wb   = (const float*)d_in[8];
    const float* gam  = (const float*)d_in[9];
    const float* bet  = (const float*)d_in[10];
    const float* mean = (const float*)d_in[11];
    const float* var  = (const float*)d_in[12];
    float* out = (float*)d_out;

    cudaFuncSetAttribute(conv3_kernel, cudaFuncAttributeMaxDynamicSharedMemorySize, 180224);
    cudaFuncSetAttribute(attn_kernel,  cudaFuncAttributeMaxDynamicSharedMemorySize, 229376);
    cudaFuncSetAttribute(out_kernel,   cudaFuncAttributeMaxDynamicSharedMemorySize, 229376);

    conv3_kernel<<<dim3(4, 3, NTILES), 256, 180224>>>(x, tw, tb, pw, pb, gw, gb);
    attn_kernel <<<dim3(8, NTILES),    256, 229376>>>();
    out_kernel  <<<dim3(8, NTILES),    256, 229376>>>(x, ww, wb, gam, bet, mean, var, out);
}

// round 2
// speedup vs baseline: 1.0943x; 1.0943x over previous
#include <cuda_runtime.h>
#include <cuda_bf16.h>
#include <mma.h>

using namespace nvcuda;

#define NTILES 128
#define C_DIM  256
#define I_DIM  128
#define HW_DIM 1024
#define KP_DIM 256

// Scratch (static device globals)
__device__ __nv_bfloat16 g_theta[(size_t)NTILES * I_DIM * HW_DIM];  // [tile][i][hw]
__device__ __nv_bfloat16 g_phi  [(size_t)NTILES * I_DIM * KP_DIM];  // [tile][i][k]
__device__ __nv_bfloat16 g_gg   [(size_t)NTILES * I_DIM * KP_DIM];  // [tile][i][k]
__device__ __nv_bfloat16 g_y    [(size_t)NTILES * HW_DIM * I_DIM];  // [tile][hw][i]

// ---------------------------------------------------------------------------
// Kernel 1: theta/phi/g 1x1 convs (GEMM) + fused 2x2 maxpool for phi/g.
// grid = (nb:4 hw-blocks of 256, mb:3, tile:128), 256 threads (8 warps).
// CTA GEMM: M=128, N=256, K=256. Padded smem; per-warp streamed epilogue.
// smem: sA [128][72]bf16 18.4KB | sB [64][264]bf16 33.8KB | buf 8*[16][68]f32 34.8KB
//   total 87KB -> 2 CTAs/SM.
// ---------------------------------------------------------------------------
#define C3_LDA 72
#define C3_LDB 264
#define C3_LDU 68

__global__ __launch_bounds__(256) void conv3_kernel(
    const float* __restrict__ x,
    const float* __restrict__ tw, const float* __restrict__ tb,
    const float* __restrict__ pw, const float* __restrict__ pb,
    const float* __restrict__ gw, const float* __restrict__ gb)
{
    extern __shared__ char smem[];
    __nv_bfloat16* sA = reinterpret_cast<__nv_bfloat16*>(smem);             // [128][72]
    __nv_bfloat16* sB = reinterpret_cast<__nv_bfloat16*>(smem + 18432);     // [64][264]
    float*         bufAll = reinterpret_cast<float*>(smem + 52224);         // 8*[16][68]

    const int nb   = blockIdx.x;
    const int mb   = blockIdx.y;
    const int tile = blockIdx.z;
    const int b = tile >> 4, t = tile & 15;
    const int bs1 = t >> 2, bs2 = t & 3;
    const int tid = threadIdx.x;
    const int warp = tid >> 5, lane = tid & 31;
    const int wr = warp >> 2, wc = warp & 3;
    float* bufW = bufAll + warp * 16 * C3_LDU;

    const float* W  = (mb == 0) ? tw : ((mb == 1) ? pw : gw);
    const float* BV = (mb == 0) ? tb : ((mb == 1) ? pb : gb);

    wmma::fragment<wmma::accumulator, 16, 16, 16, float> acc[4][4];
    #pragma unroll
    for (int i = 0; i < 4; i++)
        #pragma unroll
        for (int j = 0; j < 4; j++) wmma::fill_fragment(acc[i][j], 0.0f);

    const float* xbase = x + (size_t)b * C_DIM * 16384 + bs1 * 32 * 128 + bs2 * 32;
    const int p0 = nb * 8;

    for (int kc = 0; kc < 4; kc++) {
        // stage A: W[0..127][kc*64..+64] f32 -> bf16, padded
        #pragma unroll
        for (int it = 0; it < 8; it++) {
            int lin = it * 256 + tid;           // float4 idx among 2048
            int r = lin >> 4, c4 = (lin & 15) * 4;
            float4 v = *reinterpret_cast<const float4*>(W + r * C_DIM + kc * 64 + c4);
            __nv_bfloat16* d = sA + r * C3_LDA + c4;
            *reinterpret_cast<__nv_bfloat162*>(d)     = __floats2bfloat162_rn(v.x, v.y);
            *reinterpret_cast<__nv_bfloat162*>(d + 2) = __floats2bfloat162_rn(v.z, v.w);
        }
        // stage B: x chunk [64 c][256 hw] f32 -> bf16, padded
        #pragma unroll
        for (int it = 0; it < 16; it++) {
            int lin = it * 256 + tid;           // float4 idx among 4096
            int r = lin >> 6;
            int col = (lin & 63) * 4;
            int pp = p0 + (col >> 5);
            int qq = col & 31;
            float4 v = *reinterpret_cast<const float4*>(
                xbase + (size_t)(kc * 64 + r) * 16384 + pp * 128 + qq);
            __nv_bfloat16* d = sB + r * C3_LDB + col;
            *reinterpret_cast<__nv_bfloat162*>(d)     = __floats2bfloat162_rn(v.x, v.y);
            *reinterpret_cast<__nv_bfloat162*>(d + 2) = __floats2bfloat162_rn(v.z, v.w);
        }
        __syncthreads();
        #pragma unroll
        for (int kk = 0; kk < 4; kk++) {
            wmma::fragment<wmma::matrix_a, 16, 16, 16, __nv_bfloat16, wmma::row_major> fa[4];
            wmma::fragment<wmma::matrix_b, 16, 16, 16, __nv_bfloat16, wmma::row_major> fb[4];
            #pragma unroll
            for (int i = 0; i < 4; i++)
                wmma::load_matrix_sync(fa[i], sA + (wr * 64 + i * 16) * C3_LDA + kk * 16, C3_LDA);
            #pragma unroll
            for (int j = 0; j < 4; j++)
                wmma::load_matrix_sync(fb[j], sB + (kk * 16) * C3_LDB + wc * 64 + j * 16, C3_LDB);
            #pragma unroll
            for (int i = 0; i < 4; i++)
                #pragma unroll
                for (int j = 0; j < 4; j++)
                    wmma::mma_sync(acc[i][j], fa[i], fb[j], acc[i][j]);
        }
        __syncthreads();
    }

    // per-warp streamed epilogue: 16x64 patches
    const int hw0 = nb * 256 + wc * 64;
    for (int i = 0; i < 4; i++) {
        int o0 = wr * 64 + i * 16;
        #pragma unroll
        for (int j = 0; j < 4; j++)
            wmma::store_matrix_sync(bufW + j * 16, acc[i][j], C3_LDU, wmma::mem_row_major);
        __syncwarp();
        if (mb == 0) {
            __nv_bfloat16* dst = g_theta + (size_t)tile * I_DIM * HW_DIM;
            #pragma unroll
            for (int e = 0; e < 16; e++) {
                int pidx = e * 32 + lane;       // 512 bf16x2 pairs
                int r = pidx >> 5, col = (pidx & 31) * 2;
                float bias = BV[o0 + r];
                *reinterpret_cast<__nv_bfloat162*>(dst + (size_t)(o0 + r) * HW_DIM + hw0 + col) =
                    __floats2bfloat162_rn(bufW[r * C3_LDU + col] + bias,
                                          bufW[r * C3_LDU + col + 1] + bias);
            }
        } else {
            __nv_bfloat16* dst = ((mb == 1) ? g_phi : g_gg) + (size_t)tile * I_DIM * KP_DIM;
            int prow = nb * 4 + wc;             // pooled p index
            #pragma unroll
            for (int e = 0; e < 8; e++) {
                int idx = e * 32 + lane;        // 256 pooled outputs
                int r = idx >> 4, qp = idx & 15;
                const float* row = bufW + r * C3_LDU + 2 * qp;
                float m = fmaxf(fmaxf(row[0], row[1]), fmaxf(row[32], row[33]));
                dst[(o0 + r) * KP_DIM + prow * 16 + qp] = __float2bfloat16(m + BV[o0 + r]);
            }
        }
        __syncwarp();
    }
}

// ---------------------------------------------------------------------------
// Kernel 2: attention per (qb of 128, tile). 512 threads (16 warps).
//   S = theta_blk^T @ phi (fp32 acc -> bf16), softmax fp32, y = F @ g^T.
// smem: sT [128][136] 34.8KB | sS [128][264] 67.6KB (phi->S->F)
//       sG [128][264] 67.6KB | buf 16*[16][36]f32 36.9KB = 206.8KB.
// ---------------------------------------------------------------------------
#define AT_LDT 136
#define AT_LDS 264
#define AT_LDU 36

__global__ __launch_bounds__(512) void attn_kernel()
{
    extern __shared__ char smem[];
    __nv_bfloat16* sT = reinterpret_cast<__nv_bfloat16*>(smem);              // [128][136]
    __nv_bfloat16* sS = reinterpret_cast<__nv_bfloat16*>(smem + 34816);      // [128][264]
    __nv_bfloat16* sG = reinterpret_cast<__nv_bfloat16*>(smem + 102400);     // [128][264]
    float*         bufAll = reinterpret_cast<float*>(smem + 169984);         // 16*[16][36]

    const int qb   = blockIdx.x;
    const int tile = blockIdx.y;
    const int tid = threadIdx.x;
    const int warp = tid >> 5, lane = tid & 31;
    const int wr = warp >> 2, wc = warp & 3;
    float* bufW = bufAll + warp * 16 * AT_LDU;

    // stage theta [i][q-block] -> sT (col-major A source)
    {
        const __nv_bfloat16* thp = g_theta + (size_t)tile * I_DIM * HW_DIM + qb * 128;
        #pragma unroll
        for (int it = 0; it < 4; it++) {
            int lin = it * 512 + tid;           // uint4 among 2048 (16/row)
            int i = lin >> 4, qv = lin & 15;
            *reinterpret_cast<uint4*>(sT + i * AT_LDT + qv * 8) =
                *reinterpret_cast<const uint4*>(thp + (size_t)i * HW_DIM + qv * 8);
        }
    }
    // stage phi -> sS, g -> sG
    {
        const __nv_bfloat16* ps = g_phi + (size_t)tile * I_DIM * KP_DIM;
        const __nv_bfloat16* gs = g_gg  + (size_t)tile * I_DIM * KP_DIM;
        #pragma unroll
        for (int it = 0; it < 8; it++) {
            int lin = it * 512 + tid;           // uint4 among 4096 (32/row)
            int i = lin >> 5, k8 = (lin & 31) * 8;
            *reinterpret_cast<uint4*>(sS + i * AT_LDS + k8) =
                *reinterpret_cast<const uint4*>(ps + i * KP_DIM + k8);
            *reinterpret_cast<uint4*>(sG + i * AT_LDS + k8) =
                *reinterpret_cast<const uint4*>(gs + i * KP_DIM + k8);
        }
    }
    __syncthreads();

    // GEMM1: S[128q, 256k] = theta^T @ phi, warp tile 32x64
    wmma::fragment<wmma::accumulator, 16, 16, 16, float> acc1[2][4];
    #pragma unroll
    for (int i = 0; i < 2; i++)
        #pragma unroll
        for (int j = 0; j < 4; j++) wmma::fill_fragment(acc1[i][j], 0.0f);
    #pragma unroll
    for (int kk = 0; kk < 8; kk++) {
        wmma::fragment<wmma::matrix_a, 16, 16, 16, __nv_bfloat16, wmma::col_major> fa[2];
        wmma::fragment<wmma::matrix_b, 16, 16, 16, __nv_bfloat16, wmma::row_major> fb[4];
        #pragma unroll
        for (int i = 0; i < 2; i++)
            wmma::load_matrix_sync(fa[i], sT + (kk * 16) * AT_LDT + wr * 32 + i * 16, AT_LDT);
        #pragma unroll
        for (int j = 0; j < 4; j++)
            wmma::load_matrix_sync(fb[j], sS + (kk * 16) * AT_LDS + wc * 64 + j * 16, AT_LDS);
        #pragma unroll
        for (int i = 0; i < 2; i++)
            #pragma unroll
            for (int j = 0; j < 4; j++)
                wmma::mma_sync(acc1[i][j], fa[i], fb[j], acc1[i][j]);
    }
    __syncthreads();   // everyone done reading phi (sS) before S overwrites it

    // stream S (fp32 frags) -> bf16 into sS
    for (int i = 0; i < 2; i++) {
        int q0 = wr * 32 + i * 16;
        for (int jh = 0; jh < 2; jh++) {
            int k0 = wc * 64 + jh * 32;
            wmma::store_matrix_sync(bufW,      acc1[i][jh * 2],     AT_LDU, wmma::mem_row_major);
            wmma::store_matrix_sync(bufW + 16, acc1[i][jh * 2 + 1], AT_LDU, wmma::mem_row_major);
            __syncwarp();
            #pragma unroll
            for (int e = 0; e < 8; e++) {
                int pidx = e * 32 + lane;       // 256 pairs in 16x32
                int r = pidx >> 4, col = (pidx & 15) * 2;
                *reinterpret_cast<__nv_bfloat162*>(sS + (q0 + r) * AT_LDS + k0 + col) =
                    __floats2bfloat162_rn(bufW[r * AT_LDU + col], bufW[r * AT_LDU + col + 1]);
            }
            __syncwarp();
        }
    }
    __syncthreads();

    // softmax: 16 warps x 8 rows, k=256, fp32 math on bf16 storage
    for (int rr = 0; rr < 8; rr++) {
        int row = warp * 8 + rr;
        float v[8];
        float m = -1e30f;
        #pragma unroll
        for (int u = 0; u < 8; u++) {
            v[u] = __bfloat162float(sS[row * AT_LDS + u * 32 + lane]);
            m = fmaxf(m, v[u]);
        }
        #pragma unroll
        for (int off = 16; off > 0; off >>= 1) m = fmaxf(m, __shfl_xor_sync(0xffffffffu, m, off));
        float ssum = 0.f;
        #pragma unroll
        for (int u = 0; u < 8; u++) { v[u] = __expf(v[u] - m); ssum += v[u]; }
        #pragma unroll
        for (int off = 16; off > 0; off >>= 1) ssum += __shfl_xor_sync(0xffffffffu, ssum, off);
        float inv = 1.0f / ssum;
        #pragma unroll
        for (int u = 0; u < 8; u++)
            sS[row * AT_LDS + u * 32 + lane] = __float2bfloat16(v[u] * inv);
    }
    __syncthreads();

    // GEMM2: y[128q, 128io] = F @ g^T, warp tile 32x32
    wmma::fragment<wmma::accumulator, 16, 16, 16, float> acc2[2][2];
    #pragma unroll
    for (int i = 0; i < 2; i++)
        #pragma unroll
        for (int j = 0; j < 2; j++) wmma::fill_fragment(acc2[i][j], 0.0f);
    #pragma unroll
    for (int kk = 0; kk < 16; kk++) {
        wmma::fragment<wmma::matrix_a, 16, 16, 16, __nv_bfloat16, wmma::row_major> fa[2];
        wmma::fragment<wmma::matrix_b, 16, 16, 16, __nv_bfloat16, wmma::col_major> fb[2];
        #pragma unroll
        for (int i = 0; i < 2; i++)
            wmma::load_matrix_sync(fa[i], sS + (wr * 32 + i * 16) * AT_LDS + kk * 16, AT_LDS);
        #pragma unroll
        for (int j = 0; j < 2; j++)
            wmma::load_matrix_sync(fb[j], sG + (wc * 32 + j * 16) * AT_LDS + kk * 16, AT_LDS);
        #pragma unroll
        for (int i = 0; i < 2; i++)
            #pragma unroll
            for (int j = 0; j < 2; j++)
                wmma::mma_sync(acc2[i][j], fa[i], fb[j], acc2[i][j]);
    }

    // stream y -> global bf16 [tile][q][io]
    {
        __nv_bfloat16* yp = g_y + (size_t)tile * HW_DIM * I_DIM + (size_t)qb * 128 * I_DIM;
        int io0 = wc * 32;
        for (int i = 0; i < 2; i++) {
            int q0 = wr * 32 + i * 16;
            wmma::store_matrix_sync(bufW,      acc2[i][0], AT_LDU, wmma::mem_row_major);
            wmma::store_matrix_sync(bufW + 16, acc2[i][1], AT_LDU, wmma::mem_row_major);
            __syncwarp();
            #pragma unroll
            for (int e = 0; e < 8; e++) {
                int pidx = e * 32 + lane;
                int r = pidx >> 4, col = (pidx & 15) * 2;
                *reinterpret_cast<__nv_bfloat162*>(yp + (size_t)(q0 + r) * I_DIM + io0 + col) =
                    __floats2bfloat162_rn(bufW[r * AT_LDU + col], bufW[r * AT_LDU + col + 1]);
            }
            __syncwarp();
        }
    }
}

// ---------------------------------------------------------------------------
// Kernel 3: wy = w_w @ y^T + BN + residual + output permutation.
// grid = (nb:16 hw-blocks of 64, tile:128), 256 threads. M=256,N=64,K=128.
// smem: sW [256][136] 69.6KB | sYv [64][136] 17.4KB | buf 8*[16][36] 18.4KB
//   = 105KB -> 2 CTAs/SM.
// ---------------------------------------------------------------------------
#define OU_LDW 136
#define OU_LDY 136
#define OU_LDU 36

__global__ __launch_bounds__(256) void out_kernel(
    const float* __restrict__ x, const float* __restrict__ ww, const float* __restrict__ wb,
    const float* __restrict__ gam, const float* __restrict__ bet,
    const float* __restrict__ mean, const float* __restrict__ var,
    float* __restrict__ out)
{
    extern __shared__ char smem[];
    __nv_bfloat16* sW  = reinterpret_cast<__nv_bfloat16*>(smem);             // [256][136]
    __nv_bfloat16* sYv = reinterpret_cast<__nv_bfloat16*>(smem + 69632);     // [64][136]
    float*         bufAll = reinterpret_cast<float*>(smem + 87040);          // 8*[16][36]

    const int nb   = blockIdx.x;
    const int tile = blockIdx.y;
    const int b = tile >> 4, t = tile & 15;
    const int bs1 = t >> 2, bs2 = t & 3;
    const int tid = threadIdx.x;
    const int warp = tid >> 5, lane = tid & 31;
    const int wr = warp >> 1, wc = warp & 1;
    float* bufW = bufAll + warp * 16 * OU_LDU;

    // stage W [256][128] f32 -> bf16 padded
    #pragma unroll
    for (int it = 0; it < 32; it++) {
        int lin = it * 256 + tid;               // float4 among 8192
        int r = lin >> 5, c4 = (lin & 31) * 4;
        float4 v = *reinterpret_cast<const float4*>(ww + r * I_DIM + c4);
        __nv_bfloat16* d = sW + r * OU_LDW + c4;
        *reinterpret_cast<__nv_bfloat162*>(d)     = __floats2bfloat162_rn(v.x, v.y);
        *reinterpret_cast<__nv_bfloat162*>(d + 2) = __floats2bfloat162_rn(v.z, v.w);
    }
    // stage y block [64 hw][128 i]
    {
        const __nv_bfloat16* s = g_y + (size_t)tile * HW_DIM * I_DIM + (size_t)nb * 64 * I_DIM;
        #pragma unroll
        for (int it = 0; it < 4; it++) {
            int lin = it * 256 + tid;           // uint4 among 1024 (16/row)
            int h = lin >> 4, k8 = (lin & 15) * 8;
            *reinterpret_cast<uint4*>(sYv + h * OU_LDY + k8) =
                *reinterpret_cast<const uint4*>(s + h * I_DIM + k8);
        }
    }
    __syncthreads();

    // GEMM: wy[256o, 64hw], warp tile 64x32
    wmma::fragment<wmma::accumulator, 16, 16, 16, float> acc[4][2];
    #pragma unroll
    for (int i = 0; i < 4; i++)
        #pragma unroll
        for (int j = 0; j < 2; j++) wmma::fill_fragment(acc[i][j], 0.0f);
    #pragma unroll
    for (int kk = 0; kk < 8; kk++) {
        wmma::fragment<wmma::matrix_a, 16, 16, 16, __nv_bfloat16, wmma::row_major> fa[4];
        wmma::fragment<wmma::matrix_b, 16, 16, 16, __nv_bfloat16, wmma::col_major> fb[2];
        #pragma unroll
        for (int i = 0; i < 4; i++)
            wmma::load_matrix_sync(fa[i], sW + (wr * 64 + i * 16) * OU_LDW + kk * 16, OU_LDW);
        #pragma unroll
        for (int j = 0; j < 2; j++)
            wmma::load_matrix_sync(fb[j], sYv + (wc * 32 + j * 16) * OU_LDY + kk * 16, OU_LDY);
        #pragma unroll
        for (int i = 0; i < 4; i++)
            #pragma unroll
            for (int j = 0; j < 2; j++)
                wmma::mma_sync(acc[i][j], fa[i], fb[j], acc[i][j]);
    }

    // epilogue: BN + residual + permuted scatter, per-warp 16x32 patches
    const float* xbase = x + (size_t)b * C_DIM * 16384 + bs1 * 32 * 128 + bs2 * 32;
    float* obase = out + (size_t)b * C_DIM * 16384;
    const int p = nb * 2 + wc;                  // spatial row within 32x32 tile
    const int q = lane;
    for (int i = 0; i < 4; i++) {
        int o0 = wr * 64 + i * 16;
        wmma::store_matrix_sync(bufW,      acc[i][0], OU_LDU, wmma::mem_row_major);
        wmma::store_matrix_sync(bufW + 16, acc[i][1], OU_LDU, wmma::mem_row_major);
        __syncwarp();
        #pragma unroll
        for (int e = 0; e < 16; e++) {
            int o = o0 + e;
            float sc = gam[o] * rsqrtf(var[o] + 1e-5f);
            float base = (wb[o] - mean[o]) * sc + bet[o];
            float v = bufW[e * OU_LDU + lane] * sc + base
                    + xbase[(size_t)o * 16384 + p * 128 + q];
            int co = t * 16 + (o >> 4);
            int oh = (o & 15) * 8 + (p >> 2);
            int ow = (p & 3) * 32 + q;
            obase[(size_t)co * 16384 + (size_t)oh * 128 + ow] = v;
        }
        __syncwarp();
    }
}

// ---------------------------------------------------------------------------
extern "C" void kernel_launch(void* const* d_in, const int* in_sizes, int n_in,
                              void* d_out, int out_size)
{
    const float* x    = (const float*)d_in[0];
    const float* tw   = (const float*)d_in[1];
    const float* tb   = (const float*)d_in[2];
    const float* pw   = (const float*)d_in[3];
    const float* pb   = (const float*)d_in[4];
    const float* gw   = (const float*)d_in[5];
    const float* gb   = (const float*)d_in[6];
    const float* ww   = (const float*)d_in[7];
    const float* wb   = (const float*)d_in[8];
    const float* gam  = (const float*)d_in[9];
    const float* bet  = (const float*)d_in[10];
    const float* mean = (const float*)d_in[11];
    const float* var  = (const float*)d_in[12];
    float* out = (float*)d_out;

    cudaFuncSetAttribute(conv3_kernel, cudaFuncAttributeMaxDynamicSharedMemorySize, 87040);
    cudaFuncSetAttribute(attn_kernel,  cudaFuncAttributeMaxDynamicSharedMemorySize, 206848);
    cudaFuncSetAttribute(out_kernel,   cudaFuncAttributeMaxDynamicSharedMemorySize, 105472);

    conv3_kernel<<<dim3(4, 3, NTILES), 256, 87040>>>(x, tw, tb, pw, pb, gw, gb);
    attn_kernel <<<dim3(8, NTILES),    512, 206848>>>();
    out_kernel  <<<dim3(16, NTILES),   256, 105472>>>(x, ww, wb, gam, bet, mean, var, out);
}

// round 3
// speedup vs baseline: 1.6995x; 1.5530x over previous
#include <cuda_runtime.h>
#include <cuda_bf16.h>
#include <mma.h>

using namespace nvcuda;

#define NTILES 128
#define C_DIM  256
#define I_DIM  128
#define HW_DIM 1024
#define KP_DIM 256

// Scratch (static device globals)
__device__ __nv_bfloat16 g_theta[(size_t)NTILES * I_DIM * HW_DIM];  // [tile][i][hw]
__device__ __nv_bfloat16 g_phi  [(size_t)NTILES * I_DIM * KP_DIM];  // [tile][i][k]
__device__ __nv_bfloat16 g_gg   [(size_t)NTILES * I_DIM * KP_DIM];  // [tile][i][k]
__device__ __nv_bfloat16 g_y    [(size_t)NTILES * HW_DIM * I_DIM];  // [tile][hw][i]

// ---------------------------------------------------------------------------
// Kernel 1 (fused): theta/phi/g 1x1 convs + fused 2x2 maxpool for phi/g.
// grid = (nb:4 hw-blocks of 256, tile:128), 512 threads (16 warps).
// Stage B = x[256c][256hw] bf16 ONCE; loop mb over the 3 weight matrices.
// Warp tile 32x64 (acc[2][4]); fb loaded one at a time -> ~110 regs.
// smem: sB [256][264] 135KB | sA [128][72] 18.4KB | buf 16*[16][68]f32 69.6KB
//   total 218KB -> 1 CTA/SM (16 warps).
// ---------------------------------------------------------------------------
#define CB_LDB 264
#define CB_LDA 72
#define CB_LDU 68

__global__ __launch_bounds__(512) void conv3_kernel(
    const float* __restrict__ x,
    const float* __restrict__ tw, const float* __restrict__ tb,
    const float* __restrict__ pw, const float* __restrict__ pb,
    const float* __restrict__ gw, const float* __restrict__ gb)
{
    extern __shared__ char smem[];
    __nv_bfloat16* sB = reinterpret_cast<__nv_bfloat16*>(smem);              // [256][264]
    __nv_bfloat16* sA = reinterpret_cast<__nv_bfloat16*>(smem + 135168);     // [128][72]
    float*         bufAll = reinterpret_cast<float*>(smem + 153600);         // 16*[16][68]

    const int nb   = blockIdx.x;
    const int tile = blockIdx.y;
    const int b = tile >> 4, t = tile & 15;
    const int bs1 = t >> 2, bs2 = t & 3;
    const int tid = threadIdx.x;
    const int warp = tid >> 5, lane = tid & 31;
    const int wr = warp >> 2, wc = warp & 3;       // 4x4 warp grid: M=32, N=64
    float* bufW = bufAll + warp * 16 * CB_LDU;

    const float* xbase = x + (size_t)b * C_DIM * 16384 + bs1 * 32 * 128 + bs2 * 32;
    const int p0 = nb * 8;                          // spatial rows p0..p0+7

    // ---- stage B once: x[256 c][hw block of 256] f32 -> bf16 padded ----
    #pragma unroll
    for (int it = 0; it < 32; it++) {
        int lin = it * 512 + tid;                   // float4 idx among 16384
        int r  = lin >> 6;                          // channel 0..255
        int j4 = (lin & 63) * 4;                    // hw col (mult of 4)
        int pp = p0 + (j4 >> 5);
        int qq = j4 & 31;
        float4 v = *reinterpret_cast<const float4*>(
            xbase + (size_t)r * 16384 + pp * 128 + qq);
        __nv_bfloat16* d = sB + r * CB_LDB + j4;
        *reinterpret_cast<__nv_bfloat162*>(d)     = __floats2bfloat162_rn(v.x, v.y);
        *reinterpret_cast<__nv_bfloat162*>(d + 2) = __floats2bfloat162_rn(v.z, v.w);
    }

    const float* Ws[3] = {tw, pw, gw};
    const float* Bs[3] = {tb, pb, gb};

    for (int mb = 0; mb < 3; mb++) {
        const float* W  = Ws[mb];
        const float* BV = Bs[mb];

        wmma::fragment<wmma::accumulator, 16, 16, 16, float> acc[2][4];
        #pragma unroll
        for (int i = 0; i < 2; i++)
            #pragma unroll
            for (int j = 0; j < 4; j++) wmma::fill_fragment(acc[i][j], 0.0f);

        for (int kc = 0; kc < 4; kc++) {
            __syncthreads();    // prev sA reads (and, on mb>0, epilogues) done
            // stage A: W[0..127][kc*64..+64] -> bf16 padded
            #pragma unroll
            for (int it = 0; it < 4; it++) {
                int lin = it * 512 + tid;           // float4 idx among 2048
                int r = lin >> 4, c4 = (lin & 15) * 4;
                float4 v = *reinterpret_cast<const float4*>(W + r * C_DIM + kc * 64 + c4);
                __nv_bfloat16* d = sA + r * CB_LDA + c4;
                *reinterpret_cast<__nv_bfloat162*>(d)     = __floats2bfloat162_rn(v.x, v.y);
                *reinterpret_cast<__nv_bfloat162*>(d + 2) = __floats2bfloat162_rn(v.z, v.w);
            }
            __syncthreads();
            #pragma unroll
            for (int kk = 0; kk < 4; kk++) {
                wmma::fragment<wmma::matrix_a, 16, 16, 16, __nv_bfloat16, wmma::row_major> fa[2];
                #pragma unroll
                for (int i = 0; i < 2; i++)
                    wmma::load_matrix_sync(fa[i], sA + (wr * 32 + i * 16) * CB_LDA + kk * 16, CB_LDA);
                #pragma unroll
                for (int j = 0; j < 4; j++) {
                    wmma::fragment<wmma::matrix_b, 16, 16, 16, __nv_bfloat16, wmma::row_major> fb;
                    wmma::load_matrix_sync(fb,
                        sB + (kc * 64 + kk * 16) * CB_LDB + wc * 64 + j * 16, CB_LDB);
                    #pragma unroll
                    for (int i = 0; i < 2; i++)
                        wmma::mma_sync(acc[i][j], fa[i], fb, acc[i][j]);
                }
            }
        }

        // per-warp streamed epilogue (warp-private buf, no CTA sync needed)
        const int hw0 = nb * 256 + wc * 64;
        for (int i = 0; i < 2; i++) {
            int o0 = wr * 32 + i * 16;
            #pragma unroll
            for (int j = 0; j < 4; j++)
                wmma::store_matrix_sync(bufW + j * 16, acc[i][j], CB_LDU, wmma::mem_row_major);
            __syncwarp();
            if (mb == 0) {
                __nv_bfloat16* dst = g_theta + (size_t)tile * I_DIM * HW_DIM;
                #pragma unroll
                for (int e = 0; e < 16; e++) {      // row e, 32 lanes = 64 cols
                    float bias = BV[o0 + e];
                    *reinterpret_cast<__nv_bfloat162*>(
                        dst + (size_t)(o0 + e) * HW_DIM + hw0 + lane * 2) =
                        __floats2bfloat162_rn(bufW[e * CB_LDU + lane * 2] + bias,
                                              bufW[e * CB_LDU + lane * 2 + 1] + bias);
                }
            } else {
                __nv_bfloat16* dst = ((mb == 1) ? g_phi : g_gg) + (size_t)tile * I_DIM * KP_DIM;
                int prow = nb * 4 + wc;             // pooled spatial row
                #pragma unroll
                for (int e = 0; e < 8; e++) {
                    int idx = e * 32 + lane;        // 256 pooled outputs (16 rows x 16)
                    int r = idx >> 4, s = idx & 15;
                    const float* row = bufW + r * CB_LDU + 2 * s;
                    float m = fmaxf(fmaxf(row[0], row[1]), fmaxf(row[32], row[33]));
                    dst[(o0 + r) * KP_DIM + prow * 16 + s] = __float2bfloat16(m + BV[o0 + r]);
                }
            }
            __syncwarp();
        }
    }
}

// ---------------------------------------------------------------------------
// Kernel 2: attention per (qb of 128, tile). 512 threads (16 warps).
//   S = theta_blk^T @ phi (fp32 acc -> bf16), softmax fp32, y = F @ g^T.
// smem: sT [128][136] 34.8KB | sS [128][264] 67.6KB (phi->S->F)
//       sG [128][264] 67.6KB | buf 16*[16][36]f32 36.9KB = 206.8KB.
// ---------------------------------------------------------------------------
#define AT_LDT 136
#define AT_LDS 264
#define AT_LDU 36

__global__ __launch_bounds__(512) void attn_kernel()
{
    extern __shared__ char smem[];
    __nv_bfloat16* sT = reinterpret_cast<__nv_bfloat16*>(smem);              // [128][136]
    __nv_bfloat16* sS = reinterpret_cast<__nv_bfloat16*>(smem + 34816);      // [128][264]
    __nv_bfloat16* sG = reinterpret_cast<__nv_bfloat16*>(smem + 102400);     // [128][264]
    float*         bufAll = reinterpret_cast<float*>(smem + 169984);         // 16*[16][36]

    const int qb   = blockIdx.x;
    const int tile = blockIdx.y;
    const int tid = threadIdx.x;
    const int warp = tid >> 5, lane = tid & 31;
    const int wr = warp >> 2, wc = warp & 3;
    float* bufW = bufAll + warp * 16 * AT_LDU;

    // stage theta [i][q-block] -> sT (col-major A source)
    {
        const __nv_bfloat16* thp = g_theta + (size_t)tile * I_DIM * HW_DIM + qb * 128;
        #pragma unroll
        for (int it = 0; it < 4; it++) {
            int lin = it * 512 + tid;           // uint4 among 2048 (16/row)
            int i = lin >> 4, qv = lin & 15;
            *reinterpret_cast<uint4*>(sT + i * AT_LDT + qv * 8) =
                *reinterpret_cast<const uint4*>(thp + (size_t)i * HW_DIM + qv * 8);
        }
    }
    // stage phi -> sS, g -> sG
    {
        const __nv_bfloat16* ps = g_phi + (size_t)tile * I_DIM * KP_DIM;
        const __nv_bfloat16* gs = g_gg  + (size_t)tile * I_DIM * KP_DIM;
        #pragma unroll
        for (int it = 0; it < 8; it++) {
            int lin = it * 512 + tid;           // uint4 among 4096 (32/row)
            int i = lin >> 5, k8 = (lin & 31) * 8;
            *reinterpret_cast<uint4*>(sS + i * AT_LDS + k8) =
                *reinterpret_cast<const uint4*>(ps + i * KP_DIM + k8);
            *reinterpret_cast<uint4*>(sG + i * AT_LDS + k8) =
                *reinterpret_cast<const uint4*>(gs + i * KP_DIM + k8);
        }
    }
    __syncthreads();

    // GEMM1: S[128q, 256k] = theta^T @ phi, warp tile 32x64
    wmma::fragment<wmma::accumulator, 16, 16, 16, float> acc1[2][4];
    #pragma unroll
    for (int i = 0; i < 2; i++)
        #pragma unroll
        for (int j = 0; j < 4; j++) wmma::fill_fragment(acc1[i][j], 0.0f);
    #pragma unroll
    for (int kk = 0; kk < 8; kk++) {
        wmma::fragment<wmma::matrix_a, 16, 16, 16, __nv_bfloat16, wmma::col_major> fa[2];
        #pragma unroll
        for (int i = 0; i < 2; i++)
            wmma::load_matrix_sync(fa[i], sT + (kk * 16) * AT_LDT + wr * 32 + i * 16, AT_LDT);
        #pragma unroll
        for (int j = 0; j < 4; j++) {
            wmma::fragment<wmma::matrix_b, 16, 16, 16, __nv_bfloat16, wmma::row_major> fb;
            wmma::load_matrix_sync(fb, sS + (kk * 16) * AT_LDS + wc * 64 + j * 16, AT_LDS);
            #pragma unroll
            for (int i = 0; i < 2; i++)
                wmma::mma_sync(acc1[i][j], fa[i], fb, acc1[i][j]);
        }
    }
    __syncthreads();   // everyone done reading phi (sS) before S overwrites it

    // stream S (fp32 frags) -> bf16 into sS
    for (int i = 0; i < 2; i++) {
        int q0 = wr * 32 + i * 16;
        for (int jh = 0; jh < 2; jh++) {
            int k0 = wc * 64 + jh * 32;
            wmma::store_matrix_sync(bufW,      acc1[i][jh * 2],     AT_LDU, wmma::mem_row_major);
            wmma::store_matrix_sync(bufW + 16, acc1[i][jh * 2 + 1], AT_LDU, wmma::mem_row_major);
            __syncwarp();
            #pragma unroll
            for (int e = 0; e < 8; e++) {
                int pidx = e * 32 + lane;       // 256 pairs in 16x32
                int r = pidx >> 4, col = (pidx & 15) * 2;
                *reinterpret_cast<__nv_bfloat162*>(sS + (q0 + r) * AT_LDS + k0 + col) =
                    __floats2bfloat162_rn(bufW[r * AT_LDU + col], bufW[r * AT_LDU + col + 1]);
            }
            __syncwarp();
        }
    }
    __syncthreads();

    // softmax: 16 warps x 8 rows, k=256, fp32 math on bf16 storage
    for (int rr = 0; rr < 8; rr++) {
        int row = warp * 8 + rr;
        float v[8];
        float m = -1e30f;
        #pragma unroll
        for (int u = 0; u < 8; u++) {
            v[u] = __bfloat162float(sS[row * AT_LDS + u * 32 + lane]);
            m = fmaxf(m, v[u]);
        }
        #pragma unroll
        for (int off = 16; off > 0; off >>= 1) m = fmaxf(m, __shfl_xor_sync(0xffffffffu, m, off));
        float ssum = 0.f;
        #pragma unroll
        for (int u = 0; u < 8; u++) { v[u] = __expf(v[u] - m); ssum += v[u]; }
        #pragma unroll
        for (int off = 16; off > 0; off >>= 1) ssum += __shfl_xor_sync(0xffffffffu, ssum, off);
        float inv = 1.0f / ssum;
        #pragma unroll
        for (int u = 0; u < 8; u++)
            sS[row * AT_LDS + u * 32 + lane] = __float2bfloat16(v[u] * inv);
    }
    __syncthreads();

    // GEMM2: y[128q, 128io] = F @ g^T, warp tile 32x32
    wmma::fragment<wmma::accumulator, 16, 16, 16, float> acc2[2][2];
    #pragma unroll
    for (int i = 0; i < 2; i++)
        #pragma unroll
        for (int j = 0; j < 2; j++) wmma::fill_fragment(acc2[i][j], 0.0f);
    #pragma unroll
    for (int kk = 0; kk < 16; kk++) {
        wmma::fragment<wmma::matrix_a, 16, 16, 16, __nv_bfloat16, wmma::row_major> fa[2];
        wmma::fragment<wmma::matrix_b, 16, 16, 16, __nv_bfloat16, wmma::col_major> fb[2];
        #pragma unroll
        for (int i = 0; i < 2; i++)
            wmma::load_matrix_sync(fa[i], sS + (wr * 32 + i * 16) * AT_LDS + kk * 16, AT_LDS);
        #pragma unroll
        for (int j = 0; j < 2; j++)
            wmma::load_matrix_sync(fb[j], sG + (wc * 32 + j * 16) * AT_LDS + kk * 16, AT_LDS);
        #pragma unroll
        for (int i = 0; i < 2; i++)
            #pragma unroll
            for (int j = 0; j < 2; j++)
                wmma::mma_sync(acc2[i][j], fa[i], fb[j], acc2[i][j]);
    }

    // stream y -> global bf16 [tile][q][io]
    {
        __nv_bfloat16* yp = g_y + (size_t)tile * HW_DIM * I_DIM + (size_t)qb * 128 * I_DIM;
        int io0 = wc * 32;
        for (int i = 0; i < 2; i++) {
            int q0 = wr * 32 + i * 16;
            wmma::store_matrix_sync(bufW,      acc2[i][0], AT_LDU, wmma::mem_row_major);
            wmma::store_matrix_sync(bufW + 16, acc2[i][1], AT_LDU, wmma::mem_row_major);
            __syncwarp();
            #pragma unroll
            for (int e = 0; e < 8; e++) {
                int pidx = e * 32 + lane;
                int r = pidx >> 4, col = (pidx & 15) * 2;
                *reinterpret_cast<__nv_bfloat162*>(yp + (size_t)(q0 + r) * I_DIM + io0 + col) =
                    __floats2bfloat162_rn(bufW[r * AT_LDU + col], bufW[r * AT_LDU + col + 1]);
            }
            __syncwarp();
        }
    }
}

// ---------------------------------------------------------------------------
// Kernel 3: wy = w_w @ y^T + BN + residual + output permutation.
// grid = (nb:16 hw-blocks of 64, tile:128), 256 threads. M=256,N=64,K=128.
// smem: sW [256][136] 69.6KB | sYv [64][136] 17.4KB | buf 8*[16][36] 18.4KB
// ---------------------------------------------------------------------------
#define OU_LDW 136
#define OU_LDY 136
#define OU_LDU 36

__global__ __launch_bounds__(256) void out_kernel(
    const float* __restrict__ x, const float* __restrict__ ww, const float* __restrict__ wb,
    const float* __restrict__ gam, const float* __restrict__ bet,
    const float* __restrict__ mean, const float* __restrict__ var,
    float* __restrict__ out)
{
    extern __shared__ char smem[];
    __nv_bfloat16* sW  = reinterpret_cast<__nv_bfloat16*>(smem);             // [256][136]
    __nv_bfloat16* sYv = reinterpret_cast<__nv_bfloat16*>(smem + 69632);     // [64][136]
    float*         bufAll = reinterpret_cast<float*>(smem + 87040);          // 8*[16][36]

    const int nb   = blockIdx.x;
    const int tile = blockIdx.y;
    const int b = tile >> 4, t = tile & 15;
    const int bs1 = t >> 2, bs2 = t & 3;
    const int tid = threadIdx.x;
    const int warp = tid >> 5, lane = tid & 31;
    const int wr = warp >> 1, wc = warp & 1;
    float* bufW = bufAll + warp * 16 * OU_LDU;

    // stage W [256][128] f32 -> bf16 padded
    #pragma unroll
    for (int it = 0; it < 32; it++) {
        int lin = it * 256 + tid;               // float4 among 8192
        int r = lin >> 5, c4 = (lin & 31) * 4;
        float4 v = *reinterpret_cast<const float4*>(ww + r * I_DIM + c4);
        __nv_bfloat16* d = sW + r * OU_LDW + c4;
        *reinterpret_cast<__nv_bfloat162*>(d)     = __floats2bfloat162_rn(v.x, v.y);
        *reinterpret_cast<__nv_bfloat162*>(d + 2) = __floats2bfloat162_rn(v.z, v.w);
    }
    // stage y block [64 hw][128 i]
    {
        const __nv_bfloat16* s = g_y + (size_t)tile * HW_DIM * I_DIM + (size_t)nb * 64 * I_DIM;
        #pragma unroll
        for (int it = 0; it < 4; it++) {
            int lin = it * 256 + tid;           // uint4 among 1024 (16/row)
            int h = lin >> 4, k8 = (lin & 15) * 8;
            *reinterpret_cast<uint4*>(sYv + h * OU_LDY + k8) =
                *reinterpret_cast<const uint4*>(s + h * I_DIM + k8);
        }
    }
    __syncthreads();

    // GEMM: wy[256o, 64hw], warp tile 64x32
    wmma::fragment<wmma::accumulator, 16, 16, 16, float> acc[4][2];
    #pragma unroll
    for (int i = 0; i < 4; i++)
        #pragma unroll
        for (int j = 0; j < 2; j++) wmma::fill_fragment(acc[i][j], 0.0f);
    #pragma unroll
    for (int kk = 0; kk < 8; kk++) {
        wmma::fragment<wmma::matrix_a, 16, 16, 16, __nv_bfloat16, wmma::row_major> fa[4];
        wmma::fragment<wmma::matrix_b, 16, 16, 16, __nv_bfloat16, wmma::col_major> fb[2];
        #pragma unroll
        for (int i = 0; i < 4; i++)
            wmma::load_matrix_sync(fa[i], sW + (wr * 64 + i * 16) * OU_LDW + kk * 16, OU_LDW);
        #pragma unroll
        for (int j = 0; j < 2; j++)
            wmma::load_matrix_sync(fb[j], sYv + (wc * 32 + j * 16) * OU_LDY + kk * 16, OU_LDY);
        #pragma unroll
        for (int i = 0; i < 4; i++)
            #pragma unroll
            for (int j = 0; j < 2; j++)
                wmma::mma_sync(acc[i][j], fa[i], fb[j], acc[i][j]);
    }

    // epilogue: BN + residual + permuted scatter, per-warp 16x32 patches
    const float* xbase = x + (size_t)b * C_DIM * 16384 + bs1 * 32 * 128 + bs2 * 32;
    float* obase = out + (size_t)b * C_DIM * 16384;
    const int p = nb * 2 + wc;                  // spatial row within 32x32 tile
    const int q = lane;
    for (int i = 0; i < 4; i++) {
        int o0 = wr * 64 + i * 16;
        wmma::store_matrix_sync(bufW,      acc[i][0], OU_LDU, wmma::mem_row_major);
        wmma::store_matrix_sync(bufW + 16, acc[i][1], OU_LDU, wmma::mem_row_major);
        __syncwarp();
        #pragma unroll
        for (int e = 0; e < 16; e++) {
            int o = o0 + e;
            float sc = gam[o] * rsqrtf(var[o] + 1e-5f);
            float base = (wb[o] - mean[o]) * sc + bet[o];
            float v = bufW[e * OU_LDU + lane] * sc + base
                    + xbase[(size_t)o * 16384 + p * 128 + q];
            int co = t * 16 + (o >> 4);
            int oh = (o & 15) * 8 + (p >> 2);
            int ow = (p & 3) * 32 + q;
            obase[(size_t)co * 16384 + (size_t)oh * 128 + ow] = v;
        }
        __syncwarp();
    }
}

// ---------------------------------------------------------------------------
extern "C" void kernel_launch(void* const* d_in, const int* in_sizes, int n_in,
                              void* d_out, int out_size)
{
    const float* x    = (const float*)d_in[0];
    const float* tw   = (const float*)d_in[1];
    const float* tb   = (const float*)d_in[2];
    const float* pw   = (const float*)d_in[3];
    const float* pb   = (const float*)d_in[4];
    const float* gw   = (const float*)d_in[5];
    const float* gb   = (const float*)d_in[6];
    const float* ww   = (const float*)d_in[7];
    const float* wb   = (const float*)d_in[8];
    const float* gam  = (const float*)d_in[9];
    const float* bet  = (const float*)d_in[10];
    const float* mean = (const float*)d_in[11];
    const float* var  = (const float*)d_in[12];
    float* out = (float*)d_out;

    cudaFuncSetAttribute(conv3_kernel, cudaFuncAttributeMaxDynamicSharedMemorySize, 223232);
    cudaFuncSetAttribute(attn_kernel,  cudaFuncAttributeMaxDynamicSharedMemorySize, 206848);
    cudaFuncSetAttribute(out_kernel,   cudaFuncAttributeMaxDynamicSharedMemorySize, 105472);

    conv3_kernel<<<dim3(4, NTILES),  512, 223232>>>(x, tw, tb, pw, pb, gw, gb);
    attn_kernel <<<dim3(8, NTILES),  512, 206848>>>();
    out_kernel  <<<dim3(16, NTILES), 256, 105472>>>(x, ww, wb, gam, bet, mean, var, out);
}

// round 4
// speedup vs baseline: 1.9788x; 1.1644x over previous
#include <cuda_runtime.h>
#include <cuda_bf16.h>
#include <mma.h>

using namespace nvcuda;

#define NTILES 128
#define C_DIM  256
#define I_DIM  128
#define HW_DIM 1024
#define KP_DIM 256

// Scratch (static device globals)
__device__ __nv_bfloat16 g_theta[(size_t)NTILES * I_DIM * HW_DIM];  // [tile][i][hw]
__device__ __nv_bfloat16 g_phi  [(size_t)NTILES * I_DIM * KP_DIM];  // [tile][i][k]
__device__ __nv_bfloat16 g_gg   [(size_t)NTILES * I_DIM * KP_DIM];  // [tile][i][k]
__device__ __nv_bfloat16 g_y    [(size_t)NTILES * HW_DIM * I_DIM];  // [tile][hw][i]
// Pre-converted bf16 weights
__device__ __nv_bfloat16 g_twb[I_DIM * C_DIM];
__device__ __nv_bfloat16 g_pwb[I_DIM * C_DIM];
__device__ __nv_bfloat16 g_gwb[I_DIM * C_DIM];
__device__ __nv_bfloat16 g_wwb[C_DIM * I_DIM];

// ---------------------------------------------------------------------------
// Kernel 0: convert all weights f32 -> bf16 once per launch.
// ---------------------------------------------------------------------------
__global__ void prep_kernel(const float* __restrict__ tw, const float* __restrict__ pw,
                            const float* __restrict__ gw, const float* __restrict__ ww)
{
    int i = blockIdx.x * blockDim.x + threadIdx.x;   // 0..32767
    if (i < I_DIM * C_DIM) {
        g_twb[i] = __float2bfloat16(tw[i]);
        g_pwb[i] = __float2bfloat16(pw[i]);
        g_gwb[i] = __float2bfloat16(gw[i]);
        g_wwb[i] = __float2bfloat16(ww[i]);
    }
}

// ---------------------------------------------------------------------------
// Kernel 1 (fused): theta/phi/g 1x1 convs + fused 2x2 maxpool for phi/g.
// grid = (nb:8 hw-blocks of 128, tile:128), 256 threads (8 warps).
// Stage B = x[256c][128hw] bf16 ONCE; loop mb over 3 weight matrices.
// Warp grid 4x2 (tile M=32, N=64). smem:
//   sB [256][136] 69.6KB | sA [128][72] 18.4KB | buf 8*[16][36]f32 18.4KB
//   = 106.5KB -> 2 CTAs/SM.
// ---------------------------------------------------------------------------
#define CB_LDB 136
#define CB_LDA 72
#define CB_LDU 36

__global__ __launch_bounds__(256, 2) void conv3_kernel(
    const float* __restrict__ x,
    const float* __restrict__ tb, const float* __restrict__ pb,
    const float* __restrict__ gb)
{
    extern __shared__ char smem[];
    __nv_bfloat16* sB = reinterpret_cast<__nv_bfloat16*>(smem);              // [256][136]
    __nv_bfloat16* sA = reinterpret_cast<__nv_bfloat16*>(smem + 69632);      // [128][72]
    float*         bufAll = reinterpret_cast<float*>(smem + 88064);          // 8*[16][36]

    const int nb   = blockIdx.x;                    // 0..7, 128 hw cols each
    const int tile = blockIdx.y;
    const int b = tile >> 4, t = tile & 15;
    const int bs1 = t >> 2, bs2 = t & 3;
    const int tid = threadIdx.x;
    const int warp = tid >> 5, lane = tid & 31;
    const int wr = warp >> 1, wc = warp & 1;        // 4x2 warp grid: M=32, N=64
    float* bufW = bufAll + warp * 16 * CB_LDU;

    const float* xbase = x + (size_t)b * C_DIM * 16384 + bs1 * 32 * 128 + bs2 * 32;
    const int p0 = nb * 4;                          // spatial rows p0..p0+3

    // ---- stage B once: x[256 c][hw block of 128] f32 -> bf16 padded ----
    #pragma unroll
    for (int it = 0; it < 32; it++) {
        int lin = it * 256 + tid;                   // float4 idx among 8192
        int r  = lin >> 5;                          // channel 0..255
        int j4 = (lin & 31) * 4;                    // hw col (mult of 4)
        int pp = p0 + (j4 >> 5);
        int qq = j4 & 31;
        float4 v = *reinterpret_cast<const float4*>(
            xbase + (size_t)r * 16384 + pp * 128 + qq);
        __nv_bfloat16* d = sB + r * CB_LDB + j4;
        *reinterpret_cast<__nv_bfloat162*>(d)     = __floats2bfloat162_rn(v.x, v.y);
        *reinterpret_cast<__nv_bfloat162*>(d + 2) = __floats2bfloat162_rn(v.z, v.w);
    }

    const __nv_bfloat16* Ws[3] = {g_twb, g_pwb, g_gwb};
    const float* Bs[3] = {tb, pb, gb};

    for (int mb = 0; mb < 3; mb++) {
        const __nv_bfloat16* W = Ws[mb];
        const float* BV = Bs[mb];

        wmma::fragment<wmma::accumulator, 16, 16, 16, float> acc[2][4];
        #pragma unroll
        for (int i = 0; i < 2; i++)
            #pragma unroll
            for (int j = 0; j < 4; j++) wmma::fill_fragment(acc[i][j], 0.0f);

        for (int kc = 0; kc < 4; kc++) {
            __syncthreads();    // prev sA readers done
            // stage A chunk: Wbf16[0..127][kc*64..+64] (uint4 copies)
            #pragma unroll
            for (int it = 0; it < 4; it++) {
                int lin = it * 256 + tid;           // uint4 idx among 1024
                int r = lin >> 3, c8 = (lin & 7) * 8;
                *reinterpret_cast<uint4*>(sA + r * CB_LDA + c8) =
                    *reinterpret_cast<const uint4*>(W + r * C_DIM + kc * 64 + c8);
            }
            __syncthreads();
            #pragma unroll
            for (int kk = 0; kk < 4; kk++) {
                wmma::fragment<wmma::matrix_a, 16, 16, 16, __nv_bfloat16, wmma::row_major> fa[2];
                #pragma unroll
                for (int i = 0; i < 2; i++)
                    wmma::load_matrix_sync(fa[i], sA + (wr * 32 + i * 16) * CB_LDA + kk * 16, CB_LDA);
                #pragma unroll
                for (int j = 0; j < 4; j++) {
                    wmma::fragment<wmma::matrix_b, 16, 16, 16, __nv_bfloat16, wmma::row_major> fb;
                    wmma::load_matrix_sync(fb,
                        sB + (kc * 64 + kk * 16) * CB_LDB + wc * 64 + j * 16, CB_LDB);
                    #pragma unroll
                    for (int i = 0; i < 2; i++)
                        wmma::mma_sync(acc[i][j], fa[i], fb, acc[i][j]);
                }
            }
        }

        // per-warp streamed epilogue (16x32 patches; warp-private buf)
        for (int i = 0; i < 2; i++) {
            int o0 = wr * 32 + i * 16;
            if (mb == 0) {
                __nv_bfloat16* dst = g_theta + (size_t)tile * I_DIM * HW_DIM;
                const int colbase = nb * 128 + wc * 64;
                #pragma unroll
                for (int jh = 0; jh < 2; jh++) {
                    wmma::store_matrix_sync(bufW,      acc[i][jh * 2],     CB_LDU, wmma::mem_row_major);
                    wmma::store_matrix_sync(bufW + 16, acc[i][jh * 2 + 1], CB_LDU, wmma::mem_row_major);
                    __syncwarp();
                    #pragma unroll
                    for (int e = 0; e < 8; e++) {
                        int pidx = e * 32 + lane;       // 256 bf16x2 pairs in 16x32
                        int r = pidx >> 4, col = (pidx & 15) * 2;
                        float bias = BV[o0 + r];
                        *reinterpret_cast<__nv_bfloat162*>(
                            dst + (size_t)(o0 + r) * HW_DIM + colbase + jh * 32 + col) =
                            __floats2bfloat162_rn(bufW[r * CB_LDU + col] + bias,
                                                  bufW[r * CB_LDU + col + 1] + bias);
                    }
                    __syncwarp();
                }
            } else {
                // maxpool: jh=0 covers spatial row (nb*4 + wc*2), jh=1 the next row.
                // Carry the first half's column-max in registers, combine, store.
                float hm[8];
                #pragma unroll
                for (int jh = 0; jh < 2; jh++) {
                    wmma::store_matrix_sync(bufW,      acc[i][jh * 2],     CB_LDU, wmma::mem_row_major);
                    wmma::store_matrix_sync(bufW + 16, acc[i][jh * 2 + 1], CB_LDU, wmma::mem_row_major);
                    __syncwarp();
                    #pragma unroll
                    for (int e = 0; e < 8; e++) {
                        int idx = e * 32 + lane;        // 16 rows x 16 pooled cols
                        int r = idx >> 4, s = idx & 15;
                        float mv = fmaxf(bufW[r * CB_LDU + 2 * s], bufW[r * CB_LDU + 2 * s + 1]);
                        hm[e] = (jh == 0) ? mv : fmaxf(hm[e], mv);
                    }
                    __syncwarp();
                }
                __nv_bfloat16* dst = ((mb == 1) ? g_phi : g_gg) + (size_t)tile * I_DIM * KP_DIM;
                const int prow = nb * 2 + wc;           // pooled spatial row 0..15
                #pragma unroll
                for (int e = 0; e < 8; e++) {
                    int idx = e * 32 + lane;
                    int r = idx >> 4, s = idx & 15;
                    dst[(o0 + r) * KP_DIM + prow * 16 + s] = __float2bfloat16(hm[e] + BV[o0 + r]);
                }
            }
        }
    }
}

// ---------------------------------------------------------------------------
// Kernel 2: attention per (qb of 128, tile). 512 threads (16 warps).
//   S = theta_blk^T @ phi (fp32 acc -> bf16), softmax fp32, y = F @ g^T.
// smem: sT [128][136] 34.8KB | sS [128][264] 67.6KB (phi->S->F)
//       sG [128][264] 67.6KB | buf 16*[16][36]f32 36.9KB = 206.8KB.
// ---------------------------------------------------------------------------
#define AT_LDT 136
#define AT_LDS 264
#define AT_LDU 36

__global__ __launch_bounds__(512) void attn_kernel()
{
    extern __shared__ char smem[];
    __nv_bfloat16* sT = reinterpret_cast<__nv_bfloat16*>(smem);              // [128][136]
    __nv_bfloat16* sS = reinterpret_cast<__nv_bfloat16*>(smem + 34816);      // [128][264]
    __nv_bfloat16* sG = reinterpret_cast<__nv_bfloat16*>(smem + 102400);     // [128][264]
    float*         bufAll = reinterpret_cast<float*>(smem + 169984);         // 16*[16][36]

    const int qb   = blockIdx.x;
    const int tile = blockIdx.y;
    const int tid = threadIdx.x;
    const int warp = tid >> 5, lane = tid & 31;
    const int wr = warp >> 2, wc = warp & 3;
    float* bufW = bufAll + warp * 16 * AT_LDU;

    // stage theta [i][q-block] -> sT (col-major A source)
    {
        const __nv_bfloat16* thp = g_theta + (size_t)tile * I_DIM * HW_DIM + qb * 128;
        #pragma unroll
        for (int it = 0; it < 4; it++) {
            int lin = it * 512 + tid;           // uint4 among 2048 (16/row)
            int i = lin >> 4, qv = lin & 15;
            *reinterpret_cast<uint4*>(sT + i * AT_LDT + qv * 8) =
                *reinterpret_cast<const uint4*>(thp + (size_t)i * HW_DIM + qv * 8);
        }
    }
    // stage phi -> sS, g -> sG
    {
        const __nv_bfloat16* ps = g_phi + (size_t)tile * I_DIM * KP_DIM;
        const __nv_bfloat16* gs = g_gg  + (size_t)tile * I_DIM * KP_DIM;
        #pragma unroll
        for (int it = 0; it < 8; it++) {
            int lin = it * 512 + tid;           // uint4 among 4096 (32/row)
            int i = lin >> 5, k8 = (lin & 31) * 8;
            *reinterpret_cast<uint4*>(sS + i * AT_LDS + k8) =
                *reinterpret_cast<const uint4*>(ps + i * KP_DIM + k8);
            *reinterpret_cast<uint4*>(sG + i * AT_LDS + k8) =
                *reinterpret_cast<const uint4*>(gs + i * KP_DIM + k8);
        }
    }
    __syncthreads();

    // GEMM1: S[128q, 256k] = theta^T @ phi, warp tile 32x64
    wmma::fragment<wmma::accumulator, 16, 16, 16, float> acc1[2][4];
    #pragma unroll
    for (int i = 0; i < 2; i++)
        #pragma unroll
        for (int j = 0; j < 4; j++) wmma::fill_fragment(acc1[i][j], 0.0f);
    #pragma unroll
    for (int kk = 0; kk < 8; kk++) {
        wmma::fragment<wmma::matrix_a, 16, 16, 16, __nv_bfloat16, wmma::col_major> fa[2];
        #pragma unroll
        for (int i = 0; i < 2; i++)
            wmma::load_matrix_sync(fa[i], sT + (kk * 16) * AT_LDT + wr * 32 + i * 16, AT_LDT);
        #pragma unroll
        for (int j = 0; j < 4; j++) {
            wmma::fragment<wmma::matrix_b, 16, 16, 16, __nv_bfloat16, wmma::row_major> fb;
            wmma::load_matrix_sync(fb, sS + (kk * 16) * AT_LDS + wc * 64 + j * 16, AT_LDS);
            #pragma unroll
            for (int i = 0; i < 2; i++)
                wmma::mma_sync(acc1[i][j], fa[i], fb, acc1[i][j]);
        }
    }
    __syncthreads();   // everyone done reading phi (sS) before S overwrites it

    // stream S (fp32 frags) -> bf16 into sS
    for (int i = 0; i < 2; i++) {
        int q0 = wr * 32 + i * 16;
        for (int jh = 0; jh < 2; jh++) {
            int k0 = wc * 64 + jh * 32;
            wmma::store_matrix_sync(bufW,      acc1[i][jh * 2],     AT_LDU, wmma::mem_row_major);
            wmma::store_matrix_sync(bufW + 16, acc1[i][jh * 2 + 1], AT_LDU, wmma::mem_row_major);
            __syncwarp();
            #pragma unroll
            for (int e = 0; e < 8; e++) {
                int pidx = e * 32 + lane;       // 256 pairs in 16x32
                int r = pidx >> 4, col = (pidx & 15) * 2;
                *reinterpret_cast<__nv_bfloat162*>(sS + (q0 + r) * AT_LDS + k0 + col) =
                    __floats2bfloat162_rn(bufW[r * AT_LDU + col], bufW[r * AT_LDU + col + 1]);
            }
            __syncwarp();
        }
    }
    __syncthreads();

    // softmax: 16 warps x 8 rows, k=256, fp32 math on bf16 storage
    for (int rr = 0; rr < 8; rr++) {
        int row = warp * 8 + rr;
        float v[8];
        float m = -1e30f;
        #pragma unroll
        for (int u = 0; u < 8; u++) {
            v[u] = __bfloat162float(sS[row * AT_LDS + u * 32 + lane]);
            m = fmaxf(m, v[u]);
        }
        #pragma unroll
        for (int off = 16; off > 0; off >>= 1) m = fmaxf(m, __shfl_xor_sync(0xffffffffu, m, off));
        float ssum = 0.f;
        #pragma unroll
        for (int u = 0; u < 8; u++) { v[u] = __expf(v[u] - m); ssum += v[u]; }
        #pragma unroll
        for (int off = 16; off > 0; off >>= 1) ssum += __shfl_xor_sync(0xffffffffu, ssum, off);
        float inv = 1.0f / ssum;
        #pragma unroll
        for (int u = 0; u < 8; u++)
            sS[row * AT_LDS + u * 32 + lane] = __float2bfloat16(v[u] * inv);
    }
    __syncthreads();

    // GEMM2: y[128q, 128io] = F @ g^T, warp tile 32x32
    wmma::fragment<wmma::accumulator, 16, 16, 16, float> acc2[2][2];
    #pragma unroll
    for (int i = 0; i < 2; i++)
        #pragma unroll
        for (int j = 0; j < 2; j++) wmma::fill_fragment(acc2[i][j], 0.0f);
    #pragma unroll
    for (int kk = 0; kk < 16; kk++) {
        wmma::fragment<wmma::matrix_a, 16, 16, 16, __nv_bfloat16, wmma::row_major> fa[2];
        wmma::fragment<wmma::matrix_b, 16, 16, 16, __nv_bfloat16, wmma::col_major> fb[2];
        #pragma unroll
        for (int i = 0; i < 2; i++)
            wmma::load_matrix_sync(fa[i], sS + (wr * 32 + i * 16) * AT_LDS + kk * 16, AT_LDS);
        #pragma unroll
        for (int j = 0; j < 2; j++)
            wmma::load_matrix_sync(fb[j], sG + (wc * 32 + j * 16) * AT_LDS + kk * 16, AT_LDS);
        #pragma unroll
        for (int i = 0; i < 2; i++)
            #pragma unroll
            for (int j = 0; j < 2; j++)
                wmma::mma_sync(acc2[i][j], fa[i], fb[j], acc2[i][j]);
    }

    // stream y -> global bf16 [tile][q][io]
    {
        __nv_bfloat16* yp = g_y + (size_t)tile * HW_DIM * I_DIM + (size_t)qb * 128 * I_DIM;
        int io0 = wc * 32;
        for (int i = 0; i < 2; i++) {
            int q0 = wr * 32 + i * 16;
            wmma::store_matrix_sync(bufW,      acc2[i][0], AT_LDU, wmma::mem_row_major);
            wmma::store_matrix_sync(bufW + 16, acc2[i][1], AT_LDU, wmma::mem_row_major);
            __syncwarp();
            #pragma unroll
            for (int e = 0; e < 8; e++) {
                int pidx = e * 32 + lane;
                int r = pidx >> 4, col = (pidx & 15) * 2;
                *reinterpret_cast<__nv_bfloat162*>(yp + (size_t)(q0 + r) * I_DIM + io0 + col) =
                    __floats2bfloat162_rn(bufW[r * AT_LDU + col], bufW[r * AT_LDU + col + 1]);
            }
            __syncwarp();
        }
    }
}

// ---------------------------------------------------------------------------
// Kernel 3: wy = w_w @ y^T + BN + residual + output permutation.
// grid = (nb:16 hw-blocks of 64, tile:128), 256 threads. M=256,N=64,K=128.
// smem: sW [256][136] 69.6KB | sYv [64][136] 17.4KB | buf 8*[16][36] 18.4KB
// ---------------------------------------------------------------------------
#define OU_LDW 136
#define OU_LDY 136
#define OU_LDU 36

__global__ __launch_bounds__(256) void out_kernel(
    const float* __restrict__ x, const float* __restrict__ wb,
    const float* __restrict__ gam, const float* __restrict__ bet,
    const float* __restrict__ mean, const float* __restrict__ var,
    float* __restrict__ out)
{
    extern __shared__ char smem[];
    __nv_bfloat16* sW  = reinterpret_cast<__nv_bfloat16*>(smem);             // [256][136]
    __nv_bfloat16* sYv = reinterpret_cast<__nv_bfloat16*>(smem + 69632);     // [64][136]
    float*         bufAll = reinterpret_cast<float*>(smem + 87040);          // 8*[16][36]

    const int nb   = blockIdx.x;
    const int tile = blockIdx.y;
    const int b = tile >> 4, t = tile & 15;
    const int bs1 = t >> 2, bs2 = t & 3;
    const int tid = threadIdx.x;
    const int warp = tid >> 5, lane = tid & 31;
    const int wr = warp >> 1, wc = warp & 1;
    float* bufW = bufAll + warp * 16 * OU_LDU;

    // stage W [256][128] from pre-converted bf16 (uint4 copies)
    #pragma unroll
    for (int it = 0; it < 16; it++) {
        int lin = it * 256 + tid;               // uint4 among 4096
        int r = lin >> 4, c8 = (lin & 15) * 8;
        *reinterpret_cast<uint4*>(sW + r * OU_LDW + c8) =
            *reinterpret_cast<const uint4*>(g_wwb + r * I_DIM + c8);
    }
    // stage y block [64 hw][128 i]
    {
        const __nv_bfloat16* s = g_y + (size_t)tile * HW_DIM * I_DIM + (size_t)nb * 64 * I_DIM;
        #pragma unroll
        for (int it = 0; it < 4; it++) {
            int lin = it * 256 + tid;           // uint4 among 1024 (16/row)
            int h = lin >> 4, k8 = (lin & 15) * 8;
            *reinterpret_cast<uint4*>(sYv + h * OU_LDY + k8) =
                *reinterpret_cast<const uint4*>(s + h * I_DIM + k8);
        }
    }
    __syncthreads();

    // GEMM: wy[256o, 64hw], warp tile 64x32
    wmma::fragment<wmma::accumulator, 16, 16, 16, float> acc[4][2];
    #pragma unroll
    for (int i = 0; i < 4; i++)
        #pragma unroll
        for (int j = 0; j < 2; j++) wmma::fill_fragment(acc[i][j], 0.0f);
    #pragma unroll
    for (int kk = 0; kk < 8; kk++) {
        wmma::fragment<wmma::matrix_a, 16, 16, 16, __nv_bfloat16, wmma::row_major> fa[4];
        wmma::fragment<wmma::matrix_b, 16, 16, 16, __nv_bfloat16, wmma::col_major> fb[2];
        #pragma unroll
        for (int i = 0; i < 4; i++)
            wmma::load_matrix_sync(fa[i], sW + (wr * 64 + i * 16) * OU_LDW + kk * 16, OU_LDW);
        #pragma unroll
        for (int j = 0; j < 2; j++)
            wmma::load_matrix_sync(fb[j], sYv + (wc * 32 + j * 16) * OU_LDY + kk * 16, OU_LDY);
        #pragma unroll
        for (int i = 0; i < 4; i++)
            #pragma unroll
            for (int j = 0; j < 2; j++)
                wmma::mma_sync(acc[i][j], fa[i], fb[j], acc[i][j]);
    }

    // epilogue: BN + residual + permuted scatter, per-warp 16x32 patches
    const float* xbase = x + (size_t)b * C_DIM * 16384 + bs1 * 32 * 128 + bs2 * 32;
    float* obase = out + (size_t)b * C_DIM * 16384;
    const int p = nb * 2 + wc;                  // spatial row within 32x32 tile
    const int q = lane;
    for (int i = 0; i < 4; i++) {
        int o0 = wr * 64 + i * 16;
        wmma::store_matrix_sync(bufW,      acc[i][0], OU_LDU, wmma::mem_row_major);
        wmma::store_matrix_sync(bufW + 16, acc[i][1], OU_LDU, wmma::mem_row_major);
        __syncwarp();
        #pragma unroll
        for (int e = 0; e < 16; e++) {
            int o = o0 + e;
            float sc = gam[o] * rsqrtf(var[o] + 1e-5f);
            float base = (wb[o] - mean[o]) * sc + bet[o];
            float v = bufW[e * OU_LDU + lane] * sc + base
                    + xbase[(size_t)o * 16384 + p * 128 + q];
            int co = t * 16 + (o >> 4);
            int oh = (o & 15) * 8 + (p >> 2);
            int ow = (p & 3) * 32 + q;
            obase[(size_t)co * 16384 + (size_t)oh * 128 + ow] = v;
        }
        __syncwarp();
    }
}

// ---------------------------------------------------------------------------
extern "C" void kernel_launch(void* const* d_in, const int* in_sizes, int n_in,
                              void* d_out, int out_size)
{
    const float* x    = (const float*)d_in[0];
    const float* tw   = (const float*)d_in[1];
    const float* tb   = (const float*)d_in[2];
    const float* pw   = (const float*)d_in[3];
    const float* pb   = (const float*)d_in[4];
    const float* gw   = (const float*)d_in[5];
    const float* gb   = (const float*)d_in[6];
    const float* ww   = (const float*)d_in[7];
    const float* wb   = (const float*)d_in[8];
    const float* gam  = (const float*)d_in[9];
    const float* bet  = (const float*)d_in[10];
    const float* mean = (const float*)d_in[11];
    const float* var  = (const float*)d_in[12];
    float* out = (float*)d_out;

    cudaFuncSetAttribute(conv3_kernel, cudaFuncAttributeMaxDynamicSharedMemorySize, 106496);
    cudaFuncSetAttribute(attn_kernel,  cudaFuncAttributeMaxDynamicSharedMemorySize, 206848);
    cudaFuncSetAttribute(out_kernel,   cudaFuncAttributeMaxDynamicSharedMemorySize, 105472);

    prep_kernel <<<128, 256>>>(tw, pw, gw, ww);
    conv3_kernel<<<dim3(8, NTILES),  256, 106496>>>(x, tb, pb, gb);
    attn_kernel <<<dim3(8, NTILES),  512, 206848>>>();
    out_kernel  <<<dim3(16, NTILES), 256, 105472>>>(x, wb, gam, bet, mean, var, out);
}